// round 6
// baseline (speedup 1.0000x reference)
#include <cuda_runtime.h>

// RoPE, MUFU trig + exact Cody-Waite reduction; freq table as compile-time
// constants (freq_j = 10000^(-j/32) = 10^(-j/8)), correctly-rounded fp32 via
// double literals. No fp64 at runtime, no shared memory, no __syncthreads.
//
// Mapping: one warp per 4 contiguous tokens; lane = pair index j.

#define PAIRS 32
#define TOK_PER_WARP 4
#define TPB 256

#define INV_2PI 0.15915493667125702f
#define TWO_PI_C1 6.28125f
#define TWO_PI_C2 1.9353071795864769e-3f
#define RND_MAGIC 12582912.0f

// 10^(-j/8), j = 0..31 (double literals -> correctly-rounded fp32 at compile time)
__constant__ float c_freq[PAIRS] = {
    1.0f,
    (float)0.7498942093324559,   (float)0.5623413251903491,
    (float)0.4216965034285822,   (float)0.31622776601683794,
    (float)0.23713737056616552,  (float)0.17782794100389228,
    (float)0.13335214321633237,  (float)0.1,
    (float)0.07498942093324559,  (float)0.05623413251903491,
    (float)0.04216965034285822,  (float)0.031622776601683794,
    (float)0.023713737056616552, (float)0.017782794100389228,
    (float)0.013335214321633237, (float)0.01,
    (float)0.007498942093324559, (float)0.005623413251903491,
    (float)0.004216965034285822, (float)0.0031622776601683794,
    (float)0.0023713737056616552,(float)0.0017782794100389228,
    (float)0.0013335214321633237,(float)0.001,
    (float)0.0007498942093324559,(float)0.0005623413251903491,
    (float)0.0004216965034285822,(float)0.00031622776601683794,
    (float)0.00023713737056616552,(float)0.00017782794100389228,
    (float)0.00013335214321633237
};

__device__ __forceinline__ void fast_sincos(float ang, float& s, float& c) {
    float t = __fmaf_rn(ang, INV_2PI, RND_MAGIC);
    float k = t - RND_MAGIC;
    float r = __fmaf_rn(k, -TWO_PI_C1, ang);
    r = __fmaf_rn(k, -TWO_PI_C2, r);
    s = __sinf(r);
    c = __cosf(r);
}

__global__ void __launch_bounds__(TPB) rope_const_kernel(
    const float* __restrict__ x,
    const int* __restrict__ pos,
    float* __restrict__ out,
    int n_tokens)
{
    int lane = threadIdx.x & 31;
    float freq = c_freq[lane];      // one divergent LDC per thread, once

    int warp_global = (blockIdx.x * TPB + threadIdx.x) >> 5;
    int base_token = warp_global * TOK_PER_WARP;
    if (base_token >= n_tokens) return;

    const float2* __restrict__ x2 = (const float2*)x;
    float2* __restrict__ o2 = (float2*)out;

    if (base_token + TOK_PER_WARP <= n_tokens) {
        int p[TOK_PER_WARP];
        float2 xv[TOK_PER_WARP];
#pragma unroll
        for (int i = 0; i < TOK_PER_WARP; i++)
            p[i] = __ldg(&pos[base_token + i]);
#pragma unroll
        for (int i = 0; i < TOK_PER_WARP; i++)
            xv[i] = __ldg(&x2[(size_t)(base_token + i) * PAIRS + lane]);
#pragma unroll
        for (int i = 0; i < TOK_PER_WARP; i++) {
            float ang = __fmul_rn((float)p[i], freq);
            float s, c;
            fast_sincos(ang, s, c);
            float2 ov;
            ov.x = c * xv[i].x - s * xv[i].y;
            ov.y = s * xv[i].x + c * xv[i].y;
            o2[(size_t)(base_token + i) * PAIRS + lane] = ov;
        }
    } else {
        for (int i = 0; i < TOK_PER_WARP; i++) {
            int token = base_token + i;
            if (token >= n_tokens) break;
            int pp = __ldg(&pos[token]);
            float2 xv = __ldg(&x2[(size_t)token * PAIRS + lane]);
            float ang = __fmul_rn((float)pp, freq);
            float s, c;
            fast_sincos(ang, s, c);
            float2 ov;
            ov.x = c * xv.x - s * xv.y;
            ov.y = s * xv.x + c * xv.y;
            o2[(size_t)token * PAIRS + lane] = ov;
        }
    }
}

extern "C" void kernel_launch(void* const* d_in, const int* in_sizes, int n_in,
                              void* d_out, int out_size) {
    const float* x   = (const float*)d_in[0];   // (4, 8192, 64) f32
    const int*   pos = (const int*)d_in[1];     // (4, 8192) i32
    // d_in[2] = rope_buffer — unused (trig recomputed on the fly)
    float* out = (float*)d_out;

    int n_tokens = in_sizes[1];                 // 32768
    int warps_needed = (n_tokens + TOK_PER_WARP - 1) / TOK_PER_WARP;
    int threads_needed = warps_needed * 32;
    int grid = (threads_needed + TPB - 1) / TPB;   // 1024

    rope_const_kernel<<<grid, TPB>>>(x, pos, out, n_tokens);
}

// round 7
// speedup vs baseline: 1.1429x; 1.1429x over previous
#include <cuda_runtime.h>

// RoPE, single-wave persistent-style: 296 CTAs (2/SM exactly) x 256 threads,
// each thread grid-strides over ~7 float4 elements (2 rotation pairs each),
// 2-deep load batching. MUFU trig + exact 2-term Cody-Waite reduction.
//   freq_j = 10000^(-j/32) = 10^(-j/8), compile-time correctly-rounded fp32.

#define PAIRS 32
#define TPB 256
#define GRID 296            // 148 SMs * 2 CTAs, perfectly balanced single wave

#define INV_2PI 0.15915493667125702f
#define TWO_PI_C1 6.28125f
#define TWO_PI_C2 1.9353071795864769e-3f
#define RND_MAGIC 12582912.0f

// 10^(-j/8), j = 0..31 (double literals -> correctly-rounded fp32)
__constant__ float c_freq[PAIRS] = {
    1.0f,
    (float)0.7498942093324559,   (float)0.5623413251903491,
    (float)0.4216965034285822,   (float)0.31622776601683794,
    (float)0.23713737056616552,  (float)0.17782794100389228,
    (float)0.13335214321633237,  (float)0.1,
    (float)0.07498942093324559,  (float)0.05623413251903491,
    (float)0.04216965034285822,  (float)0.031622776601683794,
    (float)0.023713737056616552, (float)0.017782794100389228,
    (float)0.013335214321633237, (float)0.01,
    (float)0.007498942093324559, (float)0.005623413251903491,
    (float)0.004216965034285822, (float)0.0031622776601683794,
    (float)0.0023713737056616552,(float)0.0017782794100389228,
    (float)0.0013335214321633237,(float)0.001,
    (float)0.0007498942093324559,(float)0.0005623413251903491,
    (float)0.0004216965034285822,(float)0.00031622776601683794,
    (float)0.00023713737056616552,(float)0.00017782794100389228,
    (float)0.00013335214321633237
};

__device__ __forceinline__ void fast_sincos(float ang, float& s, float& c) {
    float t = __fmaf_rn(ang, INV_2PI, RND_MAGIC);
    float k = t - RND_MAGIC;
    float r = __fmaf_rn(k, -TWO_PI_C1, ang);
    r = __fmaf_rn(k, -TWO_PI_C2, r);
    s = __sinf(r);
    c = __cosf(r);
}

__device__ __forceinline__ float4 rope_one(float4 xv, int g, float fp) {
    // g = float4 index; pairs 2*(g&15) and 2*(g&15)+1
    int q = (g & 15) << 1;
    float ang0 = __fmul_rn(fp, c_freq[q]);
    float ang1 = __fmul_rn(fp, c_freq[q + 1]);
    float s0, c0, s1, c1;
    fast_sincos(ang0, s0, c0);
    fast_sincos(ang1, s1, c1);
    float4 ov;
    ov.x = c0 * xv.x - s0 * xv.y;
    ov.y = s0 * xv.x + c0 * xv.y;
    ov.z = c1 * xv.z - s1 * xv.w;
    ov.w = s1 * xv.z + c1 * xv.w;
    return ov;
}

__global__ void __launch_bounds__(TPB) rope_wave_kernel(
    const float4* __restrict__ x4,
    const int* __restrict__ pos,
    float4* __restrict__ o4,
    int n_f4)
{
    int tid = blockIdx.x * TPB + threadIdx.x;
    const int stride = GRID * TPB;      // 75776

    int g = tid;
    // main loop: 2 elements per iteration, loads batched (MLP=4)
    while (g + stride < n_f4) {
        int g1 = g + stride;
        int p0 = __ldg(&pos[g >> 4]);
        int p1 = __ldg(&pos[g1 >> 4]);
        float4 xa = __ldg(&x4[g]);
        float4 xb = __ldg(&x4[g1]);
        o4[g]  = rope_one(xa, g,  (float)p0);
        o4[g1] = rope_one(xb, g1, (float)p1);
        g += 2 * stride;
    }
    if (g < n_f4) {
        int p0 = __ldg(&pos[g >> 4]);
        float4 xa = __ldg(&x4[g]);
        o4[g] = rope_one(xa, g, (float)p0);
    }
}

extern "C" void kernel_launch(void* const* d_in, const int* in_sizes, int n_in,
                              void* d_out, int out_size) {
    const float4* x4  = (const float4*)d_in[0];  // (4, 8192, 64) f32
    const int*    pos = (const int*)d_in[1];     // (4, 8192) i32
    // d_in[2] = rope_buffer — unused (trig recomputed on the fly)
    float4* o4 = (float4*)d_out;

    int n_tokens = in_sizes[1];                  // 32768
    int n_f4 = n_tokens * 16;                    // 524288

    rope_wave_kernel<<<GRID, TPB>>>(x4, pos, o4, n_f4);
}